// round 3
// baseline (speedup 1.0000x reference)
#include <cuda_runtime.h>
#include <cuda_bf16.h>

#define BATCH 8
#define CHANS 4
#define H 512
#define W 512
#define NPIX (BATCH * H * W)          // 2,097,152
#define NROWS (BATCH * H)             // 4096
#define LOSS_GRID (BATCH * (H / 4))   // 1024 blocks

typedef unsigned long long u64;

// Scratch: per-pixel horizontal distances (byte pairs: fg, bg), 127 = far.
__device__ uchar2 g_rcol[NPIX];
__device__ double g_bsum[LOSS_GRID];
__device__ unsigned g_count = 0;

// ---------------------------------------------------------------------------
// Kernel 1: horizontal capped L-inf distances. 8 rows/block, 64 thr/row,
// 8 pixels/thread via 64-bit mask windows (exact for d<=31; >31 -> 127=far).
// ---------------------------------------------------------------------------
__global__ void rowdist_kernel(const int4* __restrict__ yt4) {
    __shared__ u64 fg[8][10];   // [0] and [9] are zero guards
    __shared__ u64 bg[8][10];
    const int r = threadIdx.x >> 6;       // row in block 0..7
    const int t = threadIdx.x & 63;       // byte index 0..63 (pixels 8t..8t+7)
    const int row = blockIdx.x * 8 + r;

    const int4* p = yt4 + (size_t)row * 128 + 2 * t;
    int4 a = p[0], b = p[1];
    unsigned byte =
          (unsigned)(a.x > 0)        | ((unsigned)(a.y > 0) << 1)
        | ((unsigned)(a.z > 0) << 2) | ((unsigned)(a.w > 0) << 3)
        | ((unsigned)(b.x > 0) << 4) | ((unsigned)(b.y > 0) << 5)
        | ((unsigned)(b.z > 0) << 6) | ((unsigned)(b.w > 0) << 7);
    ((unsigned char*)&fg[r][1])[t] = (unsigned char)byte;
    if (t == 0) { fg[r][0] = 0ull; bg[r][0] = 0ull; }
    if (t == 1) { fg[r][9] = 0ull; bg[r][9] = 0ull; }
    __syncthreads();
    if (t < 8) bg[r][1 + t] = ~fg[r][1 + t];
    __syncthreads();

    const int q  = (t >> 3) + 1;          // padded u64 index
    const int sh = (t & 7) * 8;           // bit offset of this byte in F[q]
    const u64* F  = fg[r];
    const u64* Bm = bg[r];
    // Rwin: bits [8t .. 8t+63];  Lwin: bits [8t-56 .. 8t+7] with 8t+7 at MSB.
    u64 Rf = (F[q]  >> sh) | ((F[q + 1] << 1) << (63 - sh));
    u64 Lf = (F[q]  << (56 - sh)) | ((F[q - 1] >> (sh + 7)) >> 1);
    u64 Rb = (Bm[q] >> sh) | ((Bm[q + 1] << 1) << (63 - sh));
    u64 Lb = (Bm[q] << (56 - sh)) | ((Bm[q - 1] >> (sh + 7)) >> 1);

    unsigned out[4];
    #pragma unroll
    for (int j = 0; j < 8; ++j) {
        u64 tr = Rf >> j;
        int rd = tr ? (__ffsll((long long)tr) - 1) : 127;
        u64 tl = Lf << (7 - j);
        int ld = tl ? __clzll((long long)tl) : 127;
        int vfg = min(rd, ld);

        u64 ur = Rb >> j;
        int rd2 = ur ? (__ffsll((long long)ur) - 1) : 127;
        u64 ul = Lb << (7 - j);
        int ld2 = ul ? __clzll((long long)ul) : 127;
        int vbg = min(rd2, ld2);

        unsigned pair = (unsigned)vfg | ((unsigned)vbg << 8);
        out[j >> 1] = (j & 1) ? (out[j >> 1] | (pair << 16)) : pair;
    }
    ((uint4*)g_rcol)[(size_t)row * 64 + t] =
        make_uint4(out[0], out[1], out[2], out[3]);
}

// ---------------------------------------------------------------------------
// Kernel 2: vertical combine (early-exit) + softmax + weighted SE + full
// reduction (last-block pattern). 4 rows/block, 512 threads, 4 px/thread.
// ---------------------------------------------------------------------------
__global__ void loss_kernel(const float4* __restrict__ logits4,
                            float* __restrict__ out) {
    const int t = threadIdx.x & 127;      // x-quad 0..127
    const int r = threadIdx.x >> 7;       // row in block 0..3
    const int y = blockIdx.y * 4 + r;
    const int b = blockIdx.z;

    // ---- logits loads FIRST (independent, dominant DRAM traffic) ----
    const float4* lp = logits4 + ((size_t)b * CHANS * H + y) * 128 + t;
    float4 L0 = lp[0];
    float4 L1 = lp[(size_t)H * 128];
    float4 L2 = lp[2 * (size_t)H * 128];
    float4 L3 = lp[3 * (size_t)H * 128];

    // ---- softmax -> global prob per pixel (overlaps the DT loop's loads) ----
    float l0[4] = {L0.x, L0.y, L0.z, L0.w};
    float l1[4] = {L1.x, L1.y, L1.z, L1.w};
    float l2[4] = {L2.x, L2.y, L2.z, L2.w};
    float l3[4] = {L3.x, L3.y, L3.z, L3.w};
    float gp[4];
    #pragma unroll
    for (int k = 0; k < 4; ++k) {
        float m  = fmaxf(fmaxf(l0[k], l1[k]), fmaxf(l2[k], l3[k]));
        float e0 = __expf(l0[k] - m), e1 = __expf(l1[k] - m);
        float e2 = __expf(l2[k] - m), e3 = __expf(l3[k] - m);
        float inv = 1.0f / (e0 + e1 + e2 + e3);
        gp[k] = fmaxf(fmaxf(e1, e2), e3) * inv;
    }

    // ---- vertical DT with early exit ----
    union U8 { unsigned long long u; unsigned char c[8]; };
    const unsigned long long* col =
        (const unsigned long long*)g_rcol + (size_t)b * H * 128 + t;
    U8 self; self.u = col[(size_t)y * 128];
    int bfg[4], bbg[4];
    #pragma unroll
    for (int k = 0; k < 4; ++k) { bfg[k] = self.c[2*k]; bbg[k] = self.c[2*k+1]; }

    #pragma unroll 1
    for (int d = 1; d <= 30; ++d) {
        int mx = max(max(max(bfg[0], bfg[1]), max(bfg[2], bfg[3])),
                     max(max(bbg[0], bbg[1]), max(bbg[2], bbg[3])));
        if (mx <= d) break;
        U8 up, dn;
        up.u = (y - d >= 0) ? col[(size_t)(y - d) * 128] : 0x7f7f7f7f7f7f7f7full;
        dn.u = (y + d <  H) ? col[(size_t)(y + d) * 128] : 0x7f7f7f7f7f7f7f7full;
        #pragma unroll
        for (int k = 0; k < 4; ++k) {
            bfg[k] = min(bfg[k], max(d, min((int)up.c[2*k],   (int)dn.c[2*k])));
            bbg[k] = min(bbg[k], max(d, min((int)up.c[2*k+1], (int)dn.c[2*k+1])));
        }
    }

    // ---- combine ----
    float v = 0.0f;
    #pragma unroll
    for (int k = 0; k < 4; ++k) {
        float dfg = (bfg[k] <= 30) ? (float)bfg[k] : 200.0f;
        float dbg = (bbg[k] <= 30) ? (float)bbg[k] : 200.0f;
        float wmap = dfg * dfg + dbg * dbg;
        float gt = (self.c[2*k] == 0) ? 1.0f : 0.0f;
        float diff = gp[k] - gt;
        v += diff * diff * wmap;
    }

    // ---- deterministic block reduction (16 warps) ----
    #pragma unroll
    for (int o = 16; o > 0; o >>= 1) v += __shfl_down_sync(0xFFFFFFFFu, v, o);
    __shared__ float wsum[16];
    int lane = threadIdx.x & 31, wid = threadIdx.x >> 5;
    if (lane == 0) wsum[wid] = v;
    __syncthreads();

    const int bid = blockIdx.z * gridDim.y + blockIdx.y;
    __shared__ bool isLast;
    if (threadIdx.x == 0) {
        double s = 0.0;
        #pragma unroll
        for (int i = 0; i < 16; ++i) s += (double)wsum[i];
        g_bsum[bid] = s;
        __threadfence();
        unsigned prev = atomicAdd(&g_count, 1u);
        isLast = (prev == (unsigned)(LOSS_GRID - 1));
    }
    __syncthreads();

    // ---- last block: deterministic fixed-order final reduction ----
    if (isLast) {
        __shared__ double sh[512];
        double s = g_bsum[threadIdx.x] + g_bsum[threadIdx.x + 512];
        sh[threadIdx.x] = s;
        __syncthreads();
        #pragma unroll
        for (int o = 256; o > 0; o >>= 1) {
            if (threadIdx.x < o) sh[threadIdx.x] += sh[threadIdx.x + o];
            __syncthreads();
        }
        if (threadIdx.x == 0) {
            out[0] = (float)(sh[0] / (double)NPIX);
            g_count = 0;                  // reset for next graph replay
        }
    }
}

extern "C" void kernel_launch(void* const* d_in, const int* in_sizes, int n_in,
                              void* d_out, int out_size) {
    const float* logits = (const float*)d_in[0];
    const int*   y_true = (const int*)d_in[1];
    float*       out    = (float*)d_out;

    rowdist_kernel<<<NROWS / 8, 512>>>((const int4*)y_true);

    dim3 blk(512, 1, 1);
    dim3 grd(1, H / 4, BATCH);
    loss_kernel<<<grd, blk>>>((const float4*)logits, out);
}

// round 4
// speedup vs baseline: 1.0429x; 1.0429x over previous
#include <cuda_runtime.h>
#include <cuda_bf16.h>

#define BATCH 8
#define CHANS 4
#define H 512
#define W 512
#define NPIX (BATCH * H * W)          // 2,097,152
#define NROWS (BATCH * H)             // 4096
#define LOSS_BLOCKS (BATCH * (H / 2)) // 2048

typedef unsigned long long u64;

// Scratch: per-pixel horizontal distances (byte pairs: fg, bg), 127 = far.
__device__ uchar2 g_rcol[NPIX];
__device__ double g_bsum[LOSS_BLOCKS];

// ---------------------------------------------------------------------------
// Kernel 1: horizontal capped L-inf distances. 8 rows/block, 64 thr/row,
// 8 pixels/thread via 64-bit mask windows (exact for d<=31; >31 -> 127=far).
// ---------------------------------------------------------------------------
__global__ void rowdist_kernel(const int4* __restrict__ yt4) {
    __shared__ u64 fg[8][10];   // [0] and [9] are zero guards
    __shared__ u64 bg[8][10];
    const int r = threadIdx.x >> 6;       // row in block 0..7
    const int t = threadIdx.x & 63;       // byte index 0..63 (pixels 8t..8t+7)
    const int row = blockIdx.x * 8 + r;

    const int4* p = yt4 + (size_t)row * 128 + 2 * t;
    int4 a = p[0], b = p[1];
    unsigned byte =
          (unsigned)(a.x > 0)        | ((unsigned)(a.y > 0) << 1)
        | ((unsigned)(a.z > 0) << 2) | ((unsigned)(a.w > 0) << 3)
        | ((unsigned)(b.x > 0) << 4) | ((unsigned)(b.y > 0) << 5)
        | ((unsigned)(b.z > 0) << 6) | ((unsigned)(b.w > 0) << 7);
    ((unsigned char*)&fg[r][1])[t] = (unsigned char)byte;
    if (t == 0) { fg[r][0] = 0ull; bg[r][0] = 0ull; }
    if (t == 1) { fg[r][9] = 0ull; bg[r][9] = 0ull; }
    __syncthreads();
    if (t < 8) bg[r][1 + t] = ~fg[r][1 + t];
    __syncthreads();

    const int q  = (t >> 3) + 1;          // padded u64 index
    const int sh = (t & 7) * 8;           // bit offset of this byte in F[q]
    const u64* F  = fg[r];
    const u64* Bm = bg[r];
    // Rwin: bits [8t .. 8t+63];  Lwin: bits [8t-56 .. 8t+7] with 8t+7 at MSB.
    u64 Rf = (F[q]  >> sh) | ((F[q + 1] << 1) << (63 - sh));
    u64 Lf = (F[q]  << (56 - sh)) | ((F[q - 1] >> (sh + 7)) >> 1);
    u64 Rb = (Bm[q] >> sh) | ((Bm[q + 1] << 1) << (63 - sh));
    u64 Lb = (Bm[q] << (56 - sh)) | ((Bm[q - 1] >> (sh + 7)) >> 1);

    unsigned out[4];
    #pragma unroll
    for (int j = 0; j < 8; ++j) {
        u64 tr = Rf >> j;
        int rd = tr ? (__ffsll((long long)tr) - 1) : 127;
        u64 tl = Lf << (7 - j);
        int ld = tl ? __clzll((long long)tl) : 127;
        int vfg = min(rd, ld);

        u64 ur = Rb >> j;
        int rd2 = ur ? (__ffsll((long long)ur) - 1) : 127;
        u64 ul = Lb << (7 - j);
        int ld2 = ul ? __clzll((long long)ul) : 127;
        int vbg = min(rd2, ld2);

        unsigned pair = (unsigned)vfg | ((unsigned)vbg << 8);
        out[j >> 1] = (j & 1) ? (out[j >> 1] | (pair << 16)) : pair;
    }
    ((uint4*)g_rcol)[(size_t)row * 64 + t] =
        make_uint4(out[0], out[1], out[2], out[3]);
}

// ---------------------------------------------------------------------------
// Kernel 2: vertical combine (SIMD bytewise, early exit) + softmax + weighted
// squared error + per-block reduction. 2 rows/block, 256 threads, 4 px/thread.
// ---------------------------------------------------------------------------
__global__ void loss_kernel(const float4* __restrict__ logits4) {
    const int t = threadIdx.x & 127;      // x-quad 0..127
    const int r = threadIdx.x >> 7;       // row in block 0..1
    const int y = blockIdx.y * 2 + r;
    const int b = blockIdx.z;

    // ---- logits loads first (dominant DRAM traffic, max MLP) ----
    const float4* lp = logits4 + ((size_t)b * CHANS * H + y) * 128 + t;
    float4 L0 = lp[0];
    float4 L1 = lp[(size_t)H * 128];
    float4 L2 = lp[2 * (size_t)H * 128];
    float4 L3 = lp[3 * (size_t)H * 128];

    // ---- vertical DT, SIMD bytewise on interleaved (fg,bg) byte pairs ----
    const u64* col = (const u64*)g_rcol + (size_t)b * H * 128 + t;
    u64 self = col[(size_t)y * 128];
    unsigned s0 = (unsigned)self;
    unsigned s1 = (unsigned)(self >> 32);

    #pragma unroll 1
    for (int d = 1; d <= 30; ++d) {
        // all bytes <= d  <=>  no byte's MSB set after biasing (bytes <= 127)
        unsigned m = __vmaxu4(s0, s1);
        if (((m + (127 - d) * 0x01010101u) & 0x80808080u) == 0u) break;
        u64 up = (y - d >= 0) ? col[(size_t)(y - d) * 128] : 0x7f7f7f7f7f7f7f7full;
        u64 dn = (y + d <  H) ? col[(size_t)(y + d) * 128] : 0x7f7f7f7f7f7f7f7full;
        unsigned dd = (unsigned)d * 0x01010101u;
        unsigned t0 = __vminu4((unsigned)up, (unsigned)dn);
        unsigned t1 = __vminu4((unsigned)(up >> 32), (unsigned)(dn >> 32));
        s0 = __vminu4(s0, __vmaxu4(t0, dd));
        s1 = __vminu4(s1, __vmaxu4(t1, dd));
    }

    unsigned fgb[4], bgb[4];
    fgb[0] = s0 & 255u;         bgb[0] = (s0 >> 8) & 255u;
    fgb[1] = (s0 >> 16) & 255u; bgb[1] = s0 >> 24;
    fgb[2] = s1 & 255u;         bgb[2] = (s1 >> 8) & 255u;
    fgb[3] = (s1 >> 16) & 255u; bgb[3] = s1 >> 24;

    float l0[4] = {L0.x, L0.y, L0.z, L0.w};
    float l1[4] = {L1.x, L1.y, L1.z, L1.w};
    float l2[4] = {L2.x, L2.y, L2.z, L2.w};
    float l3[4] = {L3.x, L3.y, L3.z, L3.w};

    float v = 0.0f;
    #pragma unroll
    for (int k = 0; k < 4; ++k) {
        // softmax-max via 3 exps: a = max(l1,l2,l3); others = {lo, sec}
        float hi  = fmaxf(l1[k], l2[k]);
        float lo  = fminf(l1[k], l2[k]);
        float a   = fmaxf(hi, l3[k]);
        float sec = fminf(hi, l3[k]);
        float sum = 1.0f + __expf(lo - a) + __expf(sec - a) + __expf(l0[k] - a);
        float gp  = 1.0f / sum;

        float dfg = (fgb[k] <= 30u) ? (float)fgb[k] : 200.0f;
        float dbg = (bgb[k] <= 30u) ? (float)bgb[k] : 200.0f;
        float wmap = dfg * dfg + dbg * dbg;
        float gt = (fgb[k] == 0u) ? 1.0f : 0.0f;   // fg byte stays 0 iff fg pixel
        float diff = gp - gt;
        v += diff * diff * wmap;
    }

    // ---- deterministic block reduction (8 warps) ----
    #pragma unroll
    for (int o = 16; o > 0; o >>= 1) v += __shfl_down_sync(0xFFFFFFFFu, v, o);
    __shared__ float wsum[8];
    int lane = threadIdx.x & 31, wid = threadIdx.x >> 5;
    if (lane == 0) wsum[wid] = v;
    __syncthreads();
    if (threadIdx.x == 0) {
        double s = 0.0;
        #pragma unroll
        for (int i = 0; i < 8; ++i) s += (double)wsum[i];
        g_bsum[blockIdx.z * gridDim.y + blockIdx.y] = s;
    }
}

// Kernel 3: deterministic final reduction + mean.
__global__ void final_kernel(float* __restrict__ out) {
    __shared__ double sh[256];
    double s = 0.0;
    #pragma unroll
    for (int i = 0; i < LOSS_BLOCKS / 256; ++i)
        s += g_bsum[threadIdx.x + i * 256];
    sh[threadIdx.x] = s;
    __syncthreads();
    #pragma unroll
    for (int o = 128; o > 0; o >>= 1) {
        if (threadIdx.x < o) sh[threadIdx.x] += sh[threadIdx.x + o];
        __syncthreads();
    }
    if (threadIdx.x == 0) out[0] = (float)(sh[0] / (double)NPIX);
}

extern "C" void kernel_launch(void* const* d_in, const int* in_sizes, int n_in,
                              void* d_out, int out_size) {
    const float* logits = (const float*)d_in[0];
    const int*   y_true = (const int*)d_in[1];
    float*       out    = (float*)d_out;

    rowdist_kernel<<<NROWS / 8, 512>>>((const int4*)y_true);

    dim3 blk(256, 1, 1);
    dim3 grd(1, H / 2, BATCH);
    loss_kernel<<<grd, blk>>>((const float4*)logits);

    final_kernel<<<1, 256>>>(out);
}

// round 6
// speedup vs baseline: 1.2512x; 1.1997x over previous
#include <cuda_runtime.h>
#include <cuda_bf16.h>

#define BATCH 8
#define CHANS 4
#define H 512
#define W 512
#define NPIX (BATCH * H * W)          // 2,097,152
#define NROWS (BATCH * H)             // 4096
#define LOSS_BLOCKS (BATCH * (H / 2)) // 2048

typedef unsigned long long u64;

// Scratch: per-pixel horizontal distances (byte pairs: fg, bg). One of the two
// is always 0; the other is the distance to the nearest opposite-class pixel.
__device__ uchar2 g_rcol[NPIX];
__device__ double g_bsum[LOSS_BLOCKS];

// Compress nibble-bytes of a u32 (4 bytes, low nibble each) into 16 bits.
__device__ __forceinline__ unsigned nib_compress(unsigned a) {
    return (a & 0xFu) | ((a >> 4) & 0xF0u) | ((a >> 8) & 0xF00u) | ((a >> 12) & 0xF000u);
}

// ---------------------------------------------------------------------------
// Kernel 1: horizontal distance to nearest opposite-class pixel via the row
// transition bitmap. 4 rows/block, 128 thr/row, 4 px/thread.
// ---------------------------------------------------------------------------
__global__ void rowdist_kernel(const int4* __restrict__ yt4) {
    __shared__ unsigned char nib[4][128];
    __shared__ unsigned m[4][18];   // [0],[17] zero guards
    __shared__ unsigned E[4][18];   // transition map, [0],[17] zero guards
    const int tid = threadIdx.x;
    const int r = tid >> 7;           // row in block 0..3
    const int t = tid & 127;          // 0..127, pixels 4t..4t+3
    const int row = blockIdx.x * 4 + r;

    int4 v = yt4[(size_t)row * 128 + t];
    unsigned n = (unsigned)(v.x > 0) | ((unsigned)(v.y > 0) << 1)
               | ((unsigned)(v.z > 0) << 2) | ((unsigned)(v.w > 0) << 3);
    nib[r][t] = (unsigned char)n;
    if (tid < 4) {                    // guards
        m[tid][0] = 0u; m[tid][17] = 0u;
        E[tid][0] = 0u; E[tid][17] = 0u;
    }
    __syncthreads();

    if (tid < 64) {                   // 4 rows x 16 mask words
        int rr = tid >> 4, i = tid & 15;
        const unsigned* p = (const unsigned*)nib[rr];
        m[rr][i + 1] = nib_compress(p[2 * i]) | (nib_compress(p[2 * i + 1]) << 16);
    }
    __syncthreads();

    if (tid < 64) {                   // transition words: E[i] = M[i] ^ M[i+1]
        int rr = tid >> 4, i = tid & 15;
        unsigned cur = m[rr][i + 1], nxt = m[rr][i + 2];
        unsigned e = cur ^ ((cur >> 1) | (nxt << 31));
        if (i == 15) e &= 0x7fffffffu;   // no transition past the row edge
        E[rr][i + 1] = e;
    }
    __syncthreads();

    const int w   = t >> 3;           // word 0..15
    const int off = (t & 7) * 4;      // base bit of pixel quad within word

    // R64 bit k <-> E[p0+k]; sentinel at 40 => "none" -> dist > 30 (far).
    u64 R64 = ((((u64)E[r][w + 2]) << 32) | E[r][w + 1]) >> off | (1ull << 40);
    // L64 bit k <-> E[p0-32+k]; sentinel at 0 => "none" -> dist >= 32 (far).
    u64 L64 = ((((u64)E[r][w + 1]) << 32) | E[r][w]) >> off | 1ull;
    unsigned f4 = (m[r][w + 1] >> off) & 0xFu;

    u64 out = 0ull;
    #pragma unroll
    for (int j = 0; j < 4; ++j) {
        int rd = __ffsll((long long)(R64 >> j));           // 1-based = distance
        int ld = __clzll((long long)(L64 << (32 - j))) + 1;
        unsigned e = (unsigned)min(rd, ld);                // exact for e<=31
        unsigned pair = ((f4 >> j) & 1u) ? (e << 8) : e;   // (fg, bg) bytes
        out |= (u64)pair << (16 * j);
    }
    ((u64*)g_rcol)[(size_t)row * 128 + t] = out;
}

// ---------------------------------------------------------------------------
// Kernel 2: vertical combine (SIMD bytewise, early exit) + softmax + weighted
// squared error + per-block reduction. 2 rows/block, 256 threads, 4 px/thread.
// ---------------------------------------------------------------------------
__global__ void loss_kernel(const float4* __restrict__ logits4) {
    const int t = threadIdx.x & 127;      // x-quad 0..127
    const int r = threadIdx.x >> 7;       // row in block 0..1
    const int y = blockIdx.y * 2 + r;
    const int b = blockIdx.z;

    // ---- logits loads first (dominant DRAM traffic, max MLP) ----
    const float4* lp = logits4 + ((size_t)b * CHANS * H + y) * 128 + t;
    float4 L0 = lp[0];
    float4 L1 = lp[(size_t)H * 128];
    float4 L2 = lp[2 * (size_t)H * 128];
    float4 L3 = lp[3 * (size_t)H * 128];

    // ---- vertical DT, SIMD bytewise on interleaved (fg,bg) byte pairs ----
    const u64* col = (const u64*)g_rcol + (size_t)b * H * 128 + t;
    u64 self = col[(size_t)y * 128];
    unsigned s0 = (unsigned)self;
    unsigned s1 = (unsigned)(self >> 32);

    #pragma unroll 1
    for (int d = 1; d <= 30; ++d) {
        // all bytes <= d  <=>  no byte's MSB set after biasing (bytes <= 127)
        unsigned mm = __vmaxu4(s0, s1);
        if (((mm + (127 - d) * 0x01010101u) & 0x80808080u) == 0u) break;
        u64 up = (y - d >= 0) ? col[(size_t)(y - d) * 128] : 0x7f7f7f7f7f7f7f7full;
        u64 dn = (y + d <  H) ? col[(size_t)(y + d) * 128] : 0x7f7f7f7f7f7f7f7full;
        unsigned dd = (unsigned)d * 0x01010101u;
        unsigned t0 = __vminu4((unsigned)up, (unsigned)dn);
        unsigned t1 = __vminu4((unsigned)(up >> 32), (unsigned)(dn >> 32));
        s0 = __vminu4(s0, __vmaxu4(t0, dd));
        s1 = __vminu4(s1, __vmaxu4(t1, dd));
    }

    unsigned fgb[4], bgb[4];
    fgb[0] = s0 & 255u;         bgb[0] = (s0 >> 8) & 255u;
    fgb[1] = (s0 >> 16) & 255u; bgb[1] = s0 >> 24;
    fgb[2] = s1 & 255u;         bgb[2] = (s1 >> 8) & 255u;
    fgb[3] = (s1 >> 16) & 255u; bgb[3] = s1 >> 24;

    float l0[4] = {L0.x, L0.y, L0.z, L0.w};
    float l1[4] = {L1.x, L1.y, L1.z, L1.w};
    float l2[4] = {L2.x, L2.y, L2.z, L2.w};
    float l3[4] = {L3.x, L3.y, L3.z, L3.w};

    float v = 0.0f;
    #pragma unroll
    for (int k = 0; k < 4; ++k) {
        // softmax-max via 3 exps: a = max(l1,l2,l3)
        float hi  = fmaxf(l1[k], l2[k]);
        float lo  = fminf(l1[k], l2[k]);
        float a   = fmaxf(hi, l3[k]);
        float sec = fminf(hi, l3[k]);
        float sum = 1.0f + __expf(lo - a) + __expf(sec - a) + __expf(l0[k] - a);
        float gp  = 1.0f / sum;

        float dfg = (fgb[k] <= 30u) ? (float)fgb[k] : 200.0f;
        float dbg = (bgb[k] <= 30u) ? (float)bgb[k] : 200.0f;
        float wmap = dfg * dfg + dbg * dbg;
        float gt = (fgb[k] == 0u) ? 1.0f : 0.0f;
        float diff = gp - gt;
        v += diff * diff * wmap;
    }

    // ---- deterministic block reduction (8 warps) ----
    #pragma unroll
    for (int o = 16; o > 0; o >>= 1) v += __shfl_down_sync(0xFFFFFFFFu, v, o);
    __shared__ float wsum[8];
    int lane = threadIdx.x & 31, wid = threadIdx.x >> 5;
    if (lane == 0) wsum[wid] = v;
    __syncthreads();
    if (threadIdx.x == 0) {
        double s = 0.0;
        #pragma unroll
        for (int i = 0; i < 8; ++i) s += (double)wsum[i];
        g_bsum[blockIdx.z * gridDim.y + blockIdx.y] = s;
    }
}

// Kernel 3: deterministic final reduction + mean.
__global__ void final_kernel(float* __restrict__ out) {
    __shared__ double sh[256];
    double s = 0.0;
    #pragma unroll
    for (int i = 0; i < LOSS_BLOCKS / 256; ++i)
        s += g_bsum[threadIdx.x + i * 256];
    sh[threadIdx.x] = s;
    __syncthreads();
    #pragma unroll
    for (int o = 128; o > 0; o >>= 1) {
        if (threadIdx.x < o) sh[threadIdx.x] += sh[threadIdx.x + o];
        __syncthreads();
    }
    if (threadIdx.x == 0) out[0] = (float)(sh[0] / (double)NPIX);
}

extern "C" void kernel_launch(void* const* d_in, const int* in_sizes, int n_in,
                              void* d_out, int out_size) {
    const float* logits = (const float*)d_in[0];
    const int*   y_true = (const int*)d_in[1];
    float*       out    = (float*)d_out;

    rowdist_kernel<<<NROWS / 4, 512>>>((const int4*)y_true);

    dim3 blk(256, 1, 1);
    dim3 grd(1, H / 2, BATCH);
    loss_kernel<<<grd, blk>>>((const float4*)logits);

    final_kernel<<<1, 256>>>(out);
}